// round 2
// baseline (speedup 1.0000x reference)
#include <cuda_runtime.h>
#include <cstdint>

#define NN 100000
#define EE 1600000
#define DD 64   // feature dim (EMB_DIM == OUT_C == 64)

// ---------------- device scratch (no allocations allowed) ----------------
__device__ float g_A[(size_t)NN * DD];   // "t" buffer (scatter source)
__device__ float g_B[(size_t)NN * DD];   // "y" buffer (scatter dest, init = t for self-loop)
__device__ float g_dinv[NN];             // deg -> rsqrt(deg)
__device__ int   g_row[EE];
__device__ int   g_col[EE];
__device__ int   g_xidx[NN];
__device__ int   g_is64;

// ---------------- dtype detection ----------------
// x_indices is arange(N). If stored as int64, element [1] read as int64 == 1.
// If stored as int32, the same 8 bytes hold {1,2} -> value 2 + (2^32)*... != 1.
__global__ void detect_kernel(const void* xind) {
    const long long* p = (const long long*)xind;
    g_is64 = (p[1] == 1LL) ? 1 : 0;
}

// Convert ei (2 x E) and x_indices to int32 arrays (handles int32 or int64 input).
__global__ void convert_kernel(const void* ei, const void* xind) {
    int i = blockIdx.x * blockDim.x + threadIdx.x;
    int is64 = g_is64;
    if (i < EE) {
        int r, c;
        if (is64) {
            const long long* p = (const long long*)ei;
            r = (int)p[i]; c = (int)p[(size_t)EE + i];
        } else {
            const int* p = (const int*)ei;
            r = p[i]; c = p[EE + i];
        }
        g_row[i] = r; g_col[i] = c;
    }
    if (i < NN) {
        int v;
        if (is64) v = (int)((const long long*)xind)[i];
        else      v = ((const int*)xind)[i];
        g_xidx[i] = v;
    }
}

// ---------------- degree / normalization ----------------
__global__ void deg_init_kernel() {
    int i = blockIdx.x * blockDim.x + threadIdx.x;
    if (i < NN) g_dinv[i] = 1.0f;   // self-loop contributes 1 to in-degree
}

__global__ void deg_acc_kernel() {
    int e = blockIdx.x * blockDim.x + threadIdx.x;
    if (e < EE) atomicAdd(&g_dinv[g_col[e]], 1.0f);
}

__global__ void deg_fin_kernel() {
    int i = blockIdx.x * blockDim.x + threadIdx.x;
    if (i < NN) g_dinv[i] = rsqrtf(g_dinv[i]);   // deg >= 1 always
}

// ---------------- hop elementwise passes (float4 vectorized) ----------------
// Hop 0: t = s * emb[xidx]; y = t (self-loop init)
__global__ void elem0_kernel(const float4* __restrict__ emb) {
    int i = blockIdx.x * blockDim.x + threadIdx.x;   // over N*16 float4s
    if (i >= NN * (DD / 4)) return;
    int row = i >> 4;
    float s = g_dinv[row];
    float4 v = emb[(size_t)g_xidx[row] * (DD / 4) + (i & 15)];
    v.x *= s; v.y *= s; v.z *= s; v.w *= s;
    ((float4*)g_A)[i] = v;
    ((float4*)g_B)[i] = v;
}

// Hops 2..K: t = s^2 * y_prev; y = t
__global__ void elemk_kernel() {
    int i = blockIdx.x * blockDim.x + threadIdx.x;
    if (i >= NN * (DD / 4)) return;
    int row = i >> 4;
    float s = g_dinv[row];
    s = s * s;
    float4 v = ((const float4*)g_B)[i];
    v.x *= s; v.y *= s; v.z *= s; v.w *= s;
    ((float4*)g_A)[i] = v;
    ((float4*)g_B)[i] = v;
}

// ---------------- edge scatter: y[col] += t[row] ----------------
// 16 threads per edge, each moves one float4 via a 128-bit vector reduction.
__global__ void scatter_kernel() {
    int gid = blockIdx.x * blockDim.x + threadIdx.x;
    int e = gid >> 4;
    if (e >= EE) return;
    int lane = gid & 15;
    int r = g_row[e];
    int c = g_col[e];
    float4 v = ((const float4*)g_A)[(size_t)r * (DD / 4) + lane];
    float* dst = g_B + (size_t)c * DD + lane * 4;
    asm volatile("red.global.add.v4.f32 [%0], {%1,%2,%3,%4};"
                 :: "l"(dst), "f"(v.x), "f"(v.y), "f"(v.z), "f"(v.w)
                 : "memory");
}

// ---------------- final linear: out = (s .* y) @ W^T + b ----------------
// 256 threads: tid = rslot*64 + o. Block handles 32 rows (8 iters of 4 rows).
__global__ void linear_kernel(const float* __restrict__ w,
                              const float* __restrict__ b,
                              float* __restrict__ out) {
    __shared__ float wt[DD][DD + 1];   // wt[d][o] = w[o][d], padded: conflict-free
    __shared__ float xs[4][DD];
    int tid = threadIdx.x;
    for (int i = tid; i < DD * DD; i += blockDim.x)
        wt[i & (DD - 1)][i >> 6] = w[i];
    int o = tid & (DD - 1);
    int rslot = tid >> 6;
    float bias = b[o];
    int base = blockIdx.x * 32;
    for (int it = 0; it < 8; ++it) {
        int row = base + it * 4 + rslot;
        __syncthreads();
        if (row < NN) {
            float s = g_dinv[row];
            xs[rslot][o] = s * g_B[(size_t)row * DD + o];
        }
        __syncthreads();
        if (row < NN) {
            float acc = bias;
            #pragma unroll
            for (int d = 0; d < DD; ++d)
                acc += xs[rslot][d] * wt[d][o];
            out[(size_t)row * DD + o] = acc;
        }
    }
}

// ---------------- launch ----------------
extern "C" void kernel_launch(void* const* d_in, const int* in_sizes, int n_in,
                              void* d_out, int out_size) {
    const void*  x_indices = d_in[0];
    const void*  ei        = d_in[1];
    const float* emb       = (const float*)d_in[2];
    const float* lin_w     = (const float*)d_in[3];
    const float* lin_b     = (const float*)d_in[4];
    float* out = (float*)d_out;

    const int T = 256;
    detect_kernel<<<1, 1>>>(x_indices);
    convert_kernel<<<(EE + T - 1) / T, T>>>(ei, x_indices);
    deg_init_kernel<<<(NN + T - 1) / T, T>>>();
    deg_acc_kernel<<<(EE + T - 1) / T, T>>>();
    deg_fin_kernel<<<(NN + T - 1) / T, T>>>();

    const int ELEM = NN * (DD / 4);          // 1.6M float4 threads
    const long long SCAT = (long long)EE * 16;  // 25.6M threads

    // hop 1
    elem0_kernel<<<(ELEM + T - 1) / T, T>>>((const float4*)emb);
    scatter_kernel<<<(unsigned)((SCAT + T - 1) / T), T>>>();
    // hop 2
    elemk_kernel<<<(ELEM + T - 1) / T, T>>>();
    scatter_kernel<<<(unsigned)((SCAT + T - 1) / T), T>>>();
    // hop 3
    elemk_kernel<<<(ELEM + T - 1) / T, T>>>();
    scatter_kernel<<<(unsigned)((SCAT + T - 1) / T), T>>>();

    // linear epilogue (folds the trailing s scale)
    linear_kernel<<<(NN + 31) / 32, T>>>(lin_w, lin_b, out);
}

// round 3
// speedup vs baseline: 1.7005x; 1.7005x over previous
#include <cuda_runtime.h>
#include <cstdint>

#define NN 100000
#define EE 1600000
#define DD 64
#define SCAN_BLK 1024                 // elements per scan block
#define NSB ((NN + SCAN_BLK - 1) / SCAN_BLK)   // 98 scan blocks

// ---------------- device scratch ----------------
__device__ float g_A[(size_t)NN * DD];
__device__ float g_B[(size_t)NN * DD];
__device__ float g_dinv[NN];
__device__ int   g_row[EE];
__device__ int   g_col[EE];
__device__ int   g_csr[EE];        // source node per slot, grouped by target
__device__ int   g_cnt[NN];        // in-degree histogram (no self)
__device__ int   g_start[NN + 1];  // exclusive offsets
__device__ int   g_cur[NN];        // fill cursors
__device__ int   g_bsum[NSB];      // scan block sums
__device__ int   g_bpre[NSB];      // scanned block sums (exclusive)
__device__ int   g_xidx[NN];
__device__ int   g_is64;

// ---------------- dtype detection (x_indices is arange) ----------------
__global__ void detect_kernel(const void* xind) {
    const long long* p = (const long long*)xind;
    g_is64 = (p[1] == 1LL) ? 1 : 0;
}

// ---------------- zero counters ----------------
__global__ void zero_kernel() {
    int i = blockIdx.x * blockDim.x + threadIdx.x;
    if (i < NN) g_cnt[i] = 0;
    if (i == 0) g_start[NN] = EE;   // total is always EE
}

// ---------------- convert indices + histogram cols ----------------
__global__ void convert_kernel(const void* ei, const void* xind) {
    int i = blockIdx.x * blockDim.x + threadIdx.x;
    int is64 = g_is64;
    if (i < EE) {
        int r, c;
        if (is64) {
            const long long* p = (const long long*)ei;
            r = (int)p[i]; c = (int)p[(size_t)EE + i];
        } else {
            const int* p = (const int*)ei;
            r = p[i]; c = p[EE + i];
        }
        g_row[i] = r; g_col[i] = c;
        atomicAdd(&g_cnt[c], 1);
    }
    if (i < NN) {
        int v;
        if (is64) v = (int)((const long long*)xind)[i];
        else      v = ((const int*)xind)[i];
        g_xidx[i] = v;
    }
}

// ---------------- exclusive scan of g_cnt -> g_start (3 kernels) ----------------
__global__ void scan1_kernel() {
    __shared__ int sh[256];
    int b = blockIdx.x, t = threadIdx.x;
    int base = b * SCAN_BLK + t * 4;
    int v0 = (base + 0 < NN) ? g_cnt[base + 0] : 0;
    int v1 = (base + 1 < NN) ? g_cnt[base + 1] : 0;
    int v2 = (base + 2 < NN) ? g_cnt[base + 2] : 0;
    int v3 = (base + 3 < NN) ? g_cnt[base + 3] : 0;
    int tsum = v0 + v1 + v2 + v3;
    sh[t] = tsum;
    __syncthreads();
    #pragma unroll
    for (int off = 1; off < 256; off <<= 1) {
        int x = (t >= off) ? sh[t - off] : 0;
        __syncthreads();
        if (t >= off) sh[t] += x;
        __syncthreads();
    }
    int pre = (t > 0) ? sh[t - 1] : 0;   // exclusive thread offset within block
    if (base + 0 < NN) g_start[base + 0] = pre;
    if (base + 1 < NN) g_start[base + 1] = pre + v0;
    if (base + 2 < NN) g_start[base + 2] = pre + v0 + v1;
    if (base + 3 < NN) g_start[base + 3] = pre + v0 + v1 + v2;
    if (t == 255) g_bsum[b] = sh[255];
}

__global__ void scan2_kernel() {   // single block, scan NSB block sums (exclusive)
    __shared__ int sh[NSB];
    int t = threadIdx.x;
    if (t < NSB) sh[t] = g_bsum[t];
    __syncthreads();
    if (t == 0) {
        int acc = 0;
        for (int i = 0; i < NSB; ++i) { int v = sh[i]; sh[i] = acc; acc += v; }
    }
    __syncthreads();
    if (t < NSB) g_bpre[t] = sh[t];
}

__global__ void scan3_kernel() {   // finalize offsets, cursors, dinv
    int i = blockIdx.x * blockDim.x + threadIdx.x;
    if (i >= NN) return;
    int s = g_start[i] + g_bpre[i / SCAN_BLK];
    g_start[i] = s;
    g_cur[i] = s;
    g_dinv[i] = rsqrtf((float)(g_cnt[i] + 1));   // +1 self-loop
}

// ---------------- fill CSR slots ----------------
__global__ void fill_kernel() {
    int e = blockIdx.x * blockDim.x + threadIdx.x;
    if (e >= EE) return;
    int c = g_col[e];
    int pos = atomicAdd(&g_cur[c], 1);
    g_csr[pos] = g_row[e];
}

// ---------------- t0 = s * emb[xidx] ----------------
__global__ void elem0_kernel(const float4* __restrict__ emb) {
    int i = blockIdx.x * blockDim.x + threadIdx.x;
    if (i >= NN * (DD / 4)) return;
    int row = i >> 4;
    float s = g_dinv[row];
    float4 v = emb[(size_t)g_xidx[row] * (DD / 4) + (i & 15)];
    v.x *= s; v.y *= s; v.z *= s; v.w *= s;
    ((float4*)g_A)[i] = v;
}

// ---------------- gather hop: dst[c] = m * (src[c] + sum_{r in N(c)} src[r]) ----------------
// 16 threads per node (one float4 lane each). final_hop: m=1, else m=s^2.
template<int SRC_A>
__global__ void gather_kernel(int final_hop) {
    const float4* __restrict__ src = (const float4*)(SRC_A ? g_A : g_B);
    float4* __restrict__ dst = (float4*)(SRC_A ? g_B : g_A);
    int gid = blockIdx.x * blockDim.x + threadIdx.x;
    int node = gid >> 4;
    if (node >= NN) return;
    int lane = gid & 15;
    int beg = g_start[node];
    int end = g_start[node + 1];
    float4 acc = src[(size_t)node * 16 + lane];   // self-loop
    for (int j = beg; j < end; ++j) {
        int r = __ldg(&g_csr[j]);
        float4 v = src[(size_t)r * 16 + lane];
        acc.x += v.x; acc.y += v.y; acc.z += v.z; acc.w += v.w;
    }
    float s = g_dinv[node];
    float m = final_hop ? 1.0f : s * s;
    acc.x *= m; acc.y *= m; acc.z *= m; acc.w *= m;
    dst[(size_t)node * 16 + lane] = acc;
}

// ---------------- final linear: out = (s .* y) @ W^T + b ----------------
__global__ void linear_kernel(const float* __restrict__ w,
                              const float* __restrict__ b,
                              float* __restrict__ out) {
    __shared__ float wt[DD][DD + 1];
    __shared__ float xs[4][DD];
    int tid = threadIdx.x;
    for (int i = tid; i < DD * DD; i += blockDim.x)
        wt[i & (DD - 1)][i >> 6] = w[i];
    int o = tid & (DD - 1);
    int rslot = tid >> 6;
    float bias = b[o];
    int base = blockIdx.x * 32;
    for (int it = 0; it < 8; ++it) {
        int row = base + it * 4 + rslot;
        __syncthreads();
        if (row < NN) {
            float s = g_dinv[row];
            xs[rslot][o] = s * g_B[(size_t)row * DD + o];
        }
        __syncthreads();
        if (row < NN) {
            float acc = bias;
            #pragma unroll
            for (int d = 0; d < DD; ++d)
                acc += xs[rslot][d] * wt[d][o];
            out[(size_t)row * DD + o] = acc;
        }
    }
}

// ---------------- launch ----------------
extern "C" void kernel_launch(void* const* d_in, const int* in_sizes, int n_in,
                              void* d_out, int out_size) {
    const void*  x_indices = d_in[0];
    const void*  ei        = d_in[1];
    const float* emb       = (const float*)d_in[2];
    const float* lin_w     = (const float*)d_in[3];
    const float* lin_b     = (const float*)d_in[4];
    float* out = (float*)d_out;

    const int T = 256;
    detect_kernel<<<1, 1>>>(x_indices);
    zero_kernel<<<(NN + T - 1) / T, T>>>();
    convert_kernel<<<(EE + T - 1) / T, T>>>(ei, x_indices);
    scan1_kernel<<<NSB, 256>>>();
    scan2_kernel<<<1, 128>>>();
    scan3_kernel<<<(NN + T - 1) / T, T>>>();
    fill_kernel<<<(EE + T - 1) / T, T>>>();

    const int ELEM = NN * (DD / 4);
    const int GAT  = NN * 16;
    elem0_kernel<<<(ELEM + T - 1) / T, T>>>((const float4*)emb);

    gather_kernel<1><<<(GAT + T - 1) / T, T>>>(0);   // A -> B, scale s^2
    gather_kernel<0><<<(GAT + T - 1) / T, T>>>(0);   // B -> A, scale s^2
    gather_kernel<1><<<(GAT + T - 1) / T, T>>>(1);   // A -> B, no scale (linear applies s)

    linear_kernel<<<(NN + 31) / 32, T>>>(lin_w, lin_b, out);
}

// round 6
// speedup vs baseline: 2.5192x; 1.4815x over previous
#include <cuda_runtime.h>
#include <cuda_fp16.h>
#include <mma.h>
#include <cstdint>

using namespace nvcuda;

#define NN 100000
#define EE 1600000
#define DD 64
#define SCAN_BLK 1024
#define NSB ((NN + SCAN_BLK - 1) / SCAN_BLK)   // 98
#define LROWS 128

// ---------------- device scratch ----------------
__device__ __half g_A[(size_t)NN * DD];   // fp16 feature buffers
__device__ __half g_B[(size_t)NN * DD];
__device__ float g_dinv[NN];
__device__ int   g_row[EE];
__device__ int   g_col[EE];
__device__ int   g_csr[EE];
__device__ int   g_cnt[NN];
__device__ int   g_start[NN + 1];
__device__ int   g_cur[NN];
__device__ int   g_bsum[NSB];
__device__ int   g_bpre[NSB];
__device__ int   g_xidx[NN];
__device__ int   g_is64;

__device__ __forceinline__ unsigned pack2(float x, float y) {
    __half2 h = __float22half2_rn(make_float2(x, y));
    return *(unsigned*)&h;
}

// ---------------- dtype detection (x_indices is arange) ----------------
__global__ void detect_kernel(const void* xind) {
    const long long* p = (const long long*)xind;
    g_is64 = (p[1] == 1LL) ? 1 : 0;
}

__global__ void zero_kernel() {
    int i = blockIdx.x * blockDim.x + threadIdx.x;
    if (i < NN) g_cnt[i] = 0;
    if (i == 0) g_start[NN] = EE;
}

__global__ void convert_kernel(const void* ei, const void* xind) {
    int i = blockIdx.x * blockDim.x + threadIdx.x;
    int is64 = g_is64;
    if (i < EE) {
        int r, c;
        if (is64) {
            const long long* p = (const long long*)ei;
            r = (int)p[i]; c = (int)p[(size_t)EE + i];
        } else {
            const int* p = (const int*)ei;
            r = p[i]; c = p[EE + i];
        }
        g_row[i] = r; g_col[i] = c;
        atomicAdd(&g_cnt[c], 1);
    }
    if (i < NN) {
        int v;
        if (is64) v = (int)((const long long*)xind)[i];
        else      v = ((const int*)xind)[i];
        g_xidx[i] = v;
    }
}

// ---------------- exclusive scan ----------------
__global__ void scan1_kernel() {
    __shared__ int sh[256];
    int b = blockIdx.x, t = threadIdx.x;
    int base = b * SCAN_BLK + t * 4;
    int v0 = (base + 0 < NN) ? g_cnt[base + 0] : 0;
    int v1 = (base + 1 < NN) ? g_cnt[base + 1] : 0;
    int v2 = (base + 2 < NN) ? g_cnt[base + 2] : 0;
    int v3 = (base + 3 < NN) ? g_cnt[base + 3] : 0;
    int tsum = v0 + v1 + v2 + v3;
    sh[t] = tsum;
    __syncthreads();
    #pragma unroll
    for (int off = 1; off < 256; off <<= 1) {
        int x = (t >= off) ? sh[t - off] : 0;
        __syncthreads();
        if (t >= off) sh[t] += x;
        __syncthreads();
    }
    int pre = (t > 0) ? sh[t - 1] : 0;
    if (base + 0 < NN) g_start[base + 0] = pre;
    if (base + 1 < NN) g_start[base + 1] = pre + v0;
    if (base + 2 < NN) g_start[base + 2] = pre + v0 + v1;
    if (base + 3 < NN) g_start[base + 3] = pre + v0 + v1 + v2;
    if (t == 255) g_bsum[b] = sh[255];
}

__global__ void scan2_kernel() {
    __shared__ int sh[NSB];
    int t = threadIdx.x;
    if (t < NSB) sh[t] = g_bsum[t];
    __syncthreads();
    if (t == 0) {
        int acc = 0;
        for (int i = 0; i < NSB; ++i) { int v = sh[i]; sh[i] = acc; acc += v; }
    }
    __syncthreads();
    if (t < NSB) g_bpre[t] = sh[t];
}

__global__ void scan3_kernel() {
    int i = blockIdx.x * blockDim.x + threadIdx.x;
    if (i >= NN) return;
    int s = g_start[i] + g_bpre[i / SCAN_BLK];
    g_start[i] = s;
    g_cur[i] = s;
    g_dinv[i] = rsqrtf((float)(g_cnt[i] + 1));
}

__global__ void fill_kernel() {
    int e = blockIdx.x * blockDim.x + threadIdx.x;
    if (e >= EE) return;
    int c = g_col[e];
    int pos = atomicAdd(&g_cur[c], 1);
    g_csr[pos] = g_row[e];
}

// ---------------- t0 = fp16(s * emb[xidx]) ----------------
// one thread per 8 floats (one uint4 of halfs)
__global__ void elem0_kernel(const float4* __restrict__ emb) {
    int i = blockIdx.x * blockDim.x + threadIdx.x;
    if (i >= NN * 8) return;
    int row = i >> 3;
    int c = i & 7;
    float s = g_dinv[row];
    size_t base = (size_t)g_xidx[row] * 16 + c * 2;
    float4 v0 = emb[base];
    float4 v1 = emb[base + 1];
    uint4 o;
    o.x = pack2(v0.x * s, v0.y * s);
    o.y = pack2(v0.z * s, v0.w * s);
    o.z = pack2(v1.x * s, v1.y * s);
    o.w = pack2(v1.z * s, v1.w * s);
    ((uint4*)g_A)[i] = o;
}

// ---------------- gather hop (fp16 storage, fp32 accumulate) ----------------
// 8 threads per node; each lane owns 8 halfs (one uint4).
__device__ __forceinline__ void acc_u4(uint4 u, float* a) {
    float2 f;
    f = __half22float2(*(__half2*)&u.x); a[0] += f.x; a[1] += f.y;
    f = __half22float2(*(__half2*)&u.y); a[2] += f.x; a[3] += f.y;
    f = __half22float2(*(__half2*)&u.z); a[4] += f.x; a[5] += f.y;
    f = __half22float2(*(__half2*)&u.w); a[6] += f.x; a[7] += f.y;
}

template<int SRC_A>
__global__ void gather_kernel(int final_hop) {
    const uint4* __restrict__ src = (const uint4*)(SRC_A ? g_A : g_B);
    uint4* __restrict__ dst = (uint4*)(SRC_A ? g_B : g_A);
    int gid = blockIdx.x * blockDim.x + threadIdx.x;
    int node = gid >> 3;
    if (node >= NN) return;
    int lane = gid & 7;
    int beg = g_start[node];
    int end = g_start[node + 1];
    float a[8] = {0, 0, 0, 0, 0, 0, 0, 0};
    acc_u4(src[(size_t)node * 8 + lane], a);           // self-loop
    for (int j = beg; j < end; ++j) {
        int r = __ldg(&g_csr[j]);
        acc_u4(src[(size_t)r * 8 + lane], a);
    }
    float s = g_dinv[node];
    float m = final_hop ? 1.0f : s * s;
    uint4 o;
    o.x = pack2(a[0] * m, a[1] * m);
    o.y = pack2(a[2] * m, a[3] * m);
    o.z = pack2(a[4] * m, a[5] * m);
    o.w = pack2(a[6] * m, a[7] * m);
    dst[(size_t)node * 8 + lane] = o;
}

// ---------------- final linear via wmma (fp16 x fp16 -> fp32) ----------------
// out[r][o] = sum_d (s_r * x[r][d]) * w[o][d] + b[o]
// Bias folded via K-extension: A col 64 = 1.0, B row 64 = bias, K=80.
__global__ void linear_kernel(const float* __restrict__ w,
                              const float* __restrict__ b,
                              float* __restrict__ out) {
    __shared__ __half xsh[LROWS][88];   // rows x (64 feat + 1 one + 15 zero + pad)
    __shared__ __half wh[80][72];       // (64 wT + 1 bias + 15 zero) x 64 outs
    int tid = threadIdx.x;

    // weights transposed + bias row + zero pad rows
    for (int i = tid; i < 80 * 64; i += 256) {
        int d = i >> 6, o = i & 63;
        float v;
        if (d < 64)       v = w[o * 64 + d];
        else if (d == 64) v = b[o];
        else              v = 0.0f;
        wh[d][o] = __float2half(v);
    }

    int base = blockIdx.x * LROWS;
    // stage x = s .* g_B (fp16), cols 0..63
    for (int i = tid; i < LROWS * 32; i += 256) {
        int r = i >> 5, c2 = i & 31;
        int row = base + r;
        float2 f = make_float2(0.0f, 0.0f);
        if (row < NN) {
            __half2 hv = ((const __half2*)g_B)[(size_t)row * 32 + c2];
            float s = g_dinv[row];
            f = __half22float2(hv);
            f.x *= s; f.y *= s;
        }
        *(__half2*)&xsh[r][c2 * 2] = __float22half2_rn(f);
    }
    // cols 64..79: [1, 0, 0, ...]
    for (int i = tid; i < LROWS * 8; i += 256) {
        int r = i >> 3, c = ((i & 7) << 1) + 64;
        xsh[r][c]     = (c == 64) ? __float2half(1.0f) : __float2half(0.0f);
        xsh[r][c + 1] = __float2half(0.0f);
    }
    __syncthreads();

    int wid = tid >> 5;
    int row0 = base + wid * 16;
    if (row0 < NN) {   // NN % 16 == 0, so tiles never straddle the boundary
        wmma::fragment<wmma::accumulator, 16, 16, 16, float> acc[4];
        #pragma unroll
        for (int n = 0; n < 4; ++n) wmma::fill_fragment(acc[n], 0.0f);
        #pragma unroll
        for (int k = 0; k < 5; ++k) {
            wmma::fragment<wmma::matrix_a, 16, 16, 16, __half, wmma::row_major> af;
            wmma::load_matrix_sync(af, &xsh[wid * 16][k * 16], 88);
            #pragma unroll
            for (int n = 0; n < 4; ++n) {
                wmma::fragment<wmma::matrix_b, 16, 16, 16, __half, wmma::row_major> bf;
                wmma::load_matrix_sync(bf, &wh[k * 16][n * 16], 72);
                wmma::mma_sync(acc[n], af, bf, acc[n]);
            }
        }
        #pragma unroll
        for (int n = 0; n < 4; ++n)
            wmma::store_matrix_sync(out + (size_t)row0 * 64 + n * 16, acc[n],
                                    64, wmma::mem_row_major);
    }
}

// ---------------- launch ----------------
extern "C" void kernel_launch(void* const* d_in, const int* in_sizes, int n_in,
                              void* d_out, int out_size) {
    const void*  x_indices = d_in[0];
    const void*  ei        = d_in[1];
    const float* emb       = (const float*)d_in[2];
    const float* lin_w     = (const float*)d_in[3];
    const float* lin_b     = (const float*)d_in[4];
    float* out = (float*)d_out;

    const int T = 256;
    detect_kernel<<<1, 1>>>(x_indices);
    zero_kernel<<<(NN + T - 1) / T, T>>>();
    convert_kernel<<<(EE + T - 1) / T, T>>>(ei, x_indices);
    scan1_kernel<<<NSB, 256>>>();
    scan2_kernel<<<1, 128>>>();
    scan3_kernel<<<(NN + T - 1) / T, T>>>();
    fill_kernel<<<(EE + T - 1) / T, T>>>();

    const int E0 = NN * 8;     // elem0 threads
    const int GAT = NN * 8;    // 8 lanes per node
    elem0_kernel<<<(E0 + T - 1) / T, T>>>((const float4*)emb);

    gather_kernel<1><<<(GAT + T - 1) / T, T>>>(0);   // A -> B, scale s^2
    gather_kernel<0><<<(GAT + T - 1) / T, T>>>(0);   // B -> A, scale s^2
    gather_kernel<1><<<(GAT + T - 1) / T, T>>>(1);   // A -> B, no scale

    linear_kernel<<<(NN + LROWS - 1) / LROWS, 256>>>(lin_w, lin_b, out);
}